// round 4
// baseline (speedup 1.0000x reference)
#include <cuda_runtime.h>
#include <math.h>
#include <stdint.h>

// Problem constants
#define BATCH    2
#define T_SEQ    2048
#define D_MODEL  1024
#define N_HEADS  16
#define HEAD_DIM 64
#define M_TOTAL  (BATCH * T_SEQ)          // 4096 rows
#define QKV_LD   (3 * D_MODEL)            // 3072

// Scratch (allocation-free rule: __device__ globals)
__device__ float g_qkv [M_TOTAL * QKV_LD];   // [4096, 3072] : Q|K|V interleaved per row
__device__ float g_attn[M_TOTAL * D_MODEL];  // [4096, 1024] : attention output in [B,T,C]

__device__ __forceinline__ float to_tf32(float x) {
    float y;
    asm("cvt.rna.tf32.f32 %0, %1;" : "=f"(y) : "f"(x));
    return y;
}

// ---------------------------------------------------------------------------
// tf32 mma.sync GEMM: C[M,N] = A[M,K] @ B[K,N], fp32 in/out, tf32 compute.
// 128x128 block tile, 256 threads (8 warps as 2x4), warp tile 64x32 =
// 4x4 atoms of m16n8k8. K-tile 32, double-buffered smem, 1 barrier/iter.
// smem stores A/B in fragment-linear layout:
//   A: [8 m_atoms][4 ks][32 lanes][4 regs]  (4096 floats)
//   B: [16 n_atoms][4 ks][32 lanes][2 regs] (4096 floats)
// so compute-side loads are conflict-free LDS.128 / LDS.64.
// ---------------------------------------------------------------------------
#define GT_STAGE_A 4096
#define GT_STAGE_B 4096
#define GT_STAGE   (GT_STAGE_A + GT_STAGE_B)       // 8192 floats = 32 KB
#define GT_SMEM_BYTES (2 * GT_STAGE * 4)           // 64 KB

__device__ __forceinline__ void stage_load(const float* __restrict__ A,
                                           const float* __restrict__ B,
                                           int tid, int row0, int col0, int k0,
                                           int N, int K, float4* aR, float4* bR) {
#pragma unroll
    for (int i = 0; i < 4; i++) {
        int ff = tid + i * 256;
        aR[i] = *(const float4*)&A[(size_t)(row0 + (ff >> 3)) * K + k0 + (ff & 7) * 4];
        bR[i] = *(const float4*)&B[(size_t)(k0 + (ff >> 5)) * N + col0 + (ff & 31) * 4];
    }
}

__device__ __forceinline__ void stage_store(float* dst, int tid,
                                            const float4* aR, const float4* bR) {
    float* dA = dst;
    float* dB = dst + GT_STAGE_A;
    // A element (r, c): m_atom=r/16, lane=(r&7)*4 + (c&3), reg=((r>>3)&1) | ((c&4)>>1)
#pragma unroll
    for (int i = 0; i < 4; i++) {
        int ff = tid + i * 256;
        int r  = ff >> 3;
        int c4 = (ff & 7) * 4;
        int ks = c4 >> 3;
        int reg = ((r >> 3) & 1) | (((c4 >> 2) & 1) << 1);
        int lane0 = (r & 7) * 4;
        float* p = &dA[(((r >> 4) * 4 + ks) << 7) + reg];
        p[(lane0 + 0) * 4] = to_tf32(aR[i].x);
        p[(lane0 + 1) * 4] = to_tf32(aR[i].y);
        p[(lane0 + 2) * 4] = to_tf32(aR[i].z);
        p[(lane0 + 3) * 4] = to_tf32(aR[i].w);
    }
    // B element (k, n): n_atom=n/8, lane=(n&7)*4 + (k&3), reg=(k&7)>>2
#pragma unroll
    for (int i = 0; i < 4; i++) {
        int ff = tid + i * 256;
        int k  = ff >> 5;
        int n4 = (ff & 31) * 4;
        int ks = k >> 3;
        int kk = k & 7;
        int reg = kk >> 2;
        int lanek = kk & 3;
        int nbase = n4 & 7;          // 0 or 4
        int n_atom = n4 >> 3;
        float* p = &dB[((n_atom * 4 + ks) << 6) + reg];
        p[((nbase + 0) * 4 + lanek) * 2] = to_tf32(bR[i].x);
        p[((nbase + 1) * 4 + lanek) * 2] = to_tf32(bR[i].y);
        p[((nbase + 2) * 4 + lanek) * 2] = to_tf32(bR[i].z);
        p[((nbase + 3) * 4 + lanek) * 2] = to_tf32(bR[i].w);
    }
}

__global__ __launch_bounds__(256, 2) void gemm_mma(const float* __restrict__ A,
                                                   const float* __restrict__ B,
                                                   float* __restrict__ C,
                                                   int M, int N, int K) {
    extern __shared__ float gsm[];
    const int tid  = threadIdx.x;
    const int wid  = tid >> 5;
    const int lane = tid & 31;
    const int wr = wid >> 2;          // 0..1 : warp row (64 M-rows each)
    const int wc = wid & 3;           // 0..3 : warp col (32 N-cols each)
    const int g   = lane >> 2;        // groupID
    const int tig = lane & 3;         // thread-in-group
    const int row0 = blockIdx.y * 128;
    const int col0 = blockIdx.x * 128;

    float d[4][4][4];
#pragma unroll
    for (int a = 0; a < 4; a++)
#pragma unroll
        for (int b = 0; b < 4; b++)
#pragma unroll
            for (int c = 0; c < 4; c++) d[a][b][c] = 0.f;

    const int T = K >> 5;
    float4 aR[4], bR[4];

    stage_load(A, B, tid, row0, col0, 0, N, K, aR, bR);
    stage_store(gsm, tid, aR, bR);
    __syncthreads();

    for (int t = 0; t < T; t++) {
        const int s = t & 1;
        if (t + 1 < T)
            stage_load(A, B, tid, row0, col0, (t + 1) << 5, N, K, aR, bR);

        const float* cA = gsm + s * GT_STAGE;
        const float* cB = cA + GT_STAGE_A;
#pragma unroll
        for (int ks = 0; ks < 4; ks++) {
            uint32_t af[4][4];
            uint32_t bf[4][2];
#pragma unroll
            for (int ma = 0; ma < 4; ma++)
                *(uint4*)af[ma] = *(const uint4*)&cA[(((wr * 4 + ma) * 4 + ks) << 7) + lane * 4];
#pragma unroll
            for (int na = 0; na < 4; na++)
                *(uint2*)bf[na] = *(const uint2*)&cB[(((wc * 4 + na) * 4 + ks) << 6) + lane * 2];
#pragma unroll
            for (int ma = 0; ma < 4; ma++)
#pragma unroll
                for (int na = 0; na < 4; na++) {
                    asm volatile(
                        "mma.sync.aligned.m16n8k8.row.col.f32.tf32.tf32.f32 "
                        "{%0,%1,%2,%3}, {%4,%5,%6,%7}, {%8,%9}, {%0,%1,%2,%3};"
                        : "+f"(d[ma][na][0]), "+f"(d[ma][na][1]),
                          "+f"(d[ma][na][2]), "+f"(d[ma][na][3])
                        : "r"(af[ma][0]), "r"(af[ma][1]), "r"(af[ma][2]), "r"(af[ma][3]),
                          "r"(bf[na][0]), "r"(bf[na][1]));
                }
        }

        if (t + 1 < T) {
            stage_store(gsm + ((t + 1) & 1) * GT_STAGE, tid, aR, bR);
            __syncthreads();
        }
    }

    // Epilogue: C fragment (c0,c1)@(row g, col tig*2), (c2,c3)@(row g+8)
#pragma unroll
    for (int ma = 0; ma < 4; ma++) {
#pragma unroll
        for (int na = 0; na < 4; na++) {
            const int r = row0 + wr * 64 + ma * 16 + g;
            const int c = col0 + wc * 32 + na * 8 + tig * 2;
            *(float2*)&C[(size_t)r * N + c]       = make_float2(d[ma][na][0], d[ma][na][1]);
            *(float2*)&C[(size_t)(r + 8) * N + c] = make_float2(d[ma][na][2], d[ma][na][3]);
        }
    }
}

// ---------------------------------------------------------------------------
// Causal flash attention, fp32 SIMT, outer-product register tiling (R2, unchanged).
// ---------------------------------------------------------------------------
#define FA_QT 128
#define FA_KT 64
#define QS_STRIDE 132
#define KS_STRIDE 68
#define PS_STRIDE 132
#define FA_SMEM_FLOATS (64*QS_STRIDE + 64*KS_STRIDE + 64*KS_STRIDE + 64*PS_STRIDE)

__global__ __launch_bounds__(256, 2) void flash_attn_kernel() {
    extern __shared__ float sm[];
    float* Qs = sm;
    float* Ks = Qs + 64 * QS_STRIDE;
    float* Vs = Ks + 64 * KS_STRIDE;
    float* Ps = Vs + 64 * KS_STRIDE;

    const int tid = threadIdx.x;
    const int qt  = (gridDim.x - 1) - blockIdx.x;
    const int bh  = blockIdx.y;
    const int b   = bh >> 4;
    const int h   = bh & 15;

    const float* base = g_qkv + (size_t)b * T_SEQ * QKV_LD + h * HEAD_DIM;
    const float* Qg = base;
    const float* Kg = base + D_MODEL;
    const float* Vg = base + 2 * D_MODEL;

    const int tq = tid >> 4;
    const int tk = tid & 15;
    const int q0 = qt * FA_QT;

#pragma unroll
    for (int i = 0; i < 8; i++) {
        int ff = tid + i * 256;
        int r  = ff >> 4;
        int d4 = (ff & 15) * 4;
        float4 v = *(const float4*)&Qg[(size_t)(q0 + r) * QKV_LD + d4];
        Qs[(d4 + 0) * QS_STRIDE + r] = v.x;
        Qs[(d4 + 1) * QS_STRIDE + r] = v.y;
        Qs[(d4 + 2) * QS_STRIDE + r] = v.z;
        Qs[(d4 + 3) * QS_STRIDE + r] = v.w;
    }

    const float NEG_INF = __int_as_float(0xff800000u);
    const float scale = 0.125f;
    float m[8], l[8], o[8][4];
#pragma unroll
    for (int i = 0; i < 8; i++) {
        m[i] = NEG_INF; l[i] = 0.f;
#pragma unroll
        for (int j = 0; j < 4; j++) o[i][j] = 0.f;
    }

    const int nkt = 2 * qt + 2;
    for (int kt = 0; kt < nkt; kt++) {
        __syncthreads();
#pragma unroll
        for (int i = 0; i < 4; i++) {
            int ff = tid + i * 256;
            int r  = ff >> 4;
            int d4 = (ff & 15) * 4;
            float4 kv = *(const float4*)&Kg[(size_t)(kt * FA_KT + r) * QKV_LD + d4];
            Ks[(d4 + 0) * KS_STRIDE + r] = kv.x;
            Ks[(d4 + 1) * KS_STRIDE + r] = kv.y;
            Ks[(d4 + 2) * KS_STRIDE + r] = kv.z;
            Ks[(d4 + 3) * KS_STRIDE + r] = kv.w;
            float4 vv = *(const float4*)&Vg[(size_t)(kt * FA_KT + r) * QKV_LD + d4];
            *(float4*)&Vs[r * KS_STRIDE + d4] = vv;
        }
        __syncthreads();

        float s[8][4];
#pragma unroll
        for (int i = 0; i < 8; i++)
#pragma unroll
            for (int j = 0; j < 4; j++) s[i][j] = 0.f;

#pragma unroll 8
        for (int d = 0; d < 64; d++) {
            float qv[8], kv[4];
            *(float4*)&qv[0] = *(const float4*)&Qs[d * QS_STRIDE + tq * 8];
            *(float4*)&qv[4] = *(const float4*)&Qs[d * QS_STRIDE + tq * 8 + 4];
            *(float4*)&kv[0] = *(const float4*)&Ks[d * KS_STRIDE + tk * 4];
#pragma unroll
            for (int i = 0; i < 8; i++)
#pragma unroll
                for (int j = 0; j < 4; j++) s[i][j] = fmaf(qv[i], kv[j], s[i][j]);
        }

        const bool diag = (kt >= 2 * qt);
#pragma unroll
        for (int i = 0; i < 8; i++) {
            const int qg = q0 + tq * 8 + i;
#pragma unroll
            for (int j = 0; j < 4; j++) {
                s[i][j] *= scale;
                if (diag) {
                    int kg = kt * FA_KT + tk * 4 + j;
                    if (kg > qg) s[i][j] = NEG_INF;
                }
            }
        }

#pragma unroll
        for (int i = 0; i < 8; i++) {
            float tm = fmaxf(fmaxf(s[i][0], s[i][1]), fmaxf(s[i][2], s[i][3]));
            tm = fmaxf(tm, __shfl_xor_sync(0xffffffffu, tm, 1, 16));
            tm = fmaxf(tm, __shfl_xor_sync(0xffffffffu, tm, 2, 16));
            tm = fmaxf(tm, __shfl_xor_sync(0xffffffffu, tm, 4, 16));
            tm = fmaxf(tm, __shfl_xor_sync(0xffffffffu, tm, 8, 16));
            float m_new = fmaxf(m[i], tm);
            float alpha = __expf(m[i] - m_new);
            float psum = 0.f;
#pragma unroll
            for (int j = 0; j < 4; j++) {
                float p = __expf(s[i][j] - m_new);
                s[i][j] = p;
                psum += p;
            }
            psum += __shfl_xor_sync(0xffffffffu, psum, 1, 16);
            psum += __shfl_xor_sync(0xffffffffu, psum, 2, 16);
            psum += __shfl_xor_sync(0xffffffffu, psum, 4, 16);
            psum += __shfl_xor_sync(0xffffffffu, psum, 8, 16);
            l[i] = l[i] * alpha + psum;
            m[i] = m_new;
#pragma unroll
            for (int j = 0; j < 4; j++) o[i][j] *= alpha;
        }

#pragma unroll
        for (int j = 0; j < 4; j++)
#pragma unroll
            for (int i = 0; i < 8; i++)
                Ps[(tk * 4 + j) * PS_STRIDE + tq * 8 + i] = s[i][j];
        __syncthreads();

#pragma unroll 8
        for (int k = 0; k < 64; k++) {
            float pv[8], vv[4];
            *(float4*)&pv[0] = *(const float4*)&Ps[k * PS_STRIDE + tq * 8];
            *(float4*)&pv[4] = *(const float4*)&Ps[k * PS_STRIDE + tq * 8 + 4];
            *(float4*)&vv[0] = *(const float4*)&Vs[k * KS_STRIDE + tk * 4];
#pragma unroll
            for (int i = 0; i < 8; i++)
#pragma unroll
                for (int j = 0; j < 4; j++) o[i][j] = fmaf(pv[i], vv[j], o[i][j]);
        }
    }

#pragma unroll
    for (int i = 0; i < 8; i++) {
        float inv = 1.f / l[i];
        const int qg = q0 + tq * 8 + i;
        float4 c = make_float4(o[i][0] * inv, o[i][1] * inv, o[i][2] * inv, o[i][3] * inv);
        *(float4*)&g_attn[(size_t)(b * T_SEQ + qg) * D_MODEL + h * HEAD_DIM + tk * 4] = c;
    }
}

// ---------------------------------------------------------------------------
// Launch
// ---------------------------------------------------------------------------
extern "C" void kernel_launch(void* const* d_in, const int* in_sizes, int n_in,
                              void* d_out, int out_size) {
    const float* x     = (const float*)d_in[0];   // [2,2048,1024]
    const float* w_qkv = (const float*)d_in[1];   // [1024,3072]
    const float* w_out = (const float*)d_in[2];   // [1024,1024]
    float* out = (float*)d_out;                   // [2,2048,1024]

    void* qkv_ptr = nullptr;
    void* attn_ptr = nullptr;
    cudaGetSymbolAddress(&qkv_ptr, g_qkv);
    cudaGetSymbolAddress(&attn_ptr, g_attn);

    const int fa_smem = FA_SMEM_FLOATS * (int)sizeof(float);   // 102400 B
    cudaFuncSetAttribute(flash_attn_kernel,
                         cudaFuncAttributeMaxDynamicSharedMemorySize, fa_smem);
    cudaFuncSetAttribute(gemm_mma,
                         cudaFuncAttributeMaxDynamicSharedMemorySize, GT_SMEM_BYTES);

    // 1) QKV projection: [4096,1024] @ [1024,3072] (tf32 mma.sync)
    gemm_mma<<<dim3(QKV_LD / 128, M_TOTAL / 128), 256, GT_SMEM_BYTES>>>(
        x, w_qkv, (float*)qkv_ptr, M_TOTAL, QKV_LD, D_MODEL);

    // 2) causal flash attention per (b,h)
    flash_attn_kernel<<<dim3(T_SEQ / FA_QT, BATCH * N_HEADS), 256, fa_smem>>>();

    // 3) output projection: [4096,1024] @ [1024,1024] (tf32 mma.sync)
    gemm_mma<<<dim3(D_MODEL / 128, M_TOTAL / 128), 256, GT_SMEM_BYTES>>>(
        (const float*)attn_ptr, w_out, out, M_TOTAL, D_MODEL, D_MODEL);
}

// round 5
// speedup vs baseline: 1.7813x; 1.7813x over previous
#include <cuda_runtime.h>
#include <math.h>
#include <stdint.h>

// Problem constants
#define BATCH    2
#define T_SEQ    2048
#define D_MODEL  1024
#define N_HEADS  16
#define HEAD_DIM 64
#define M_TOTAL  (BATCH * T_SEQ)          // 4096 rows
#define QKV_LD   (3 * D_MODEL)            // 3072

// Scratch (allocation-free rule: __device__ globals)
__device__ float g_qkv   [M_TOTAL * QKV_LD];    // [4096, 3072]
__device__ float g_attn  [M_TOTAL * D_MODEL];   // [4096, 1024] (tf32-rounded by flash)
__device__ float g_xr    [M_TOTAL * D_MODEL];   // tf32-rounded x
__device__ float g_wqkv_r[D_MODEL * QKV_LD];    // tf32-rounded w_qkv
__device__ float g_wout_r[D_MODEL * D_MODEL];   // tf32-rounded w_out

__device__ __forceinline__ float to_tf32(float x) {
    float y;
    asm("cvt.rna.tf32.f32 %0, %1;" : "=f"(y) : "f"(x));
    return y;
}
__device__ __forceinline__ uint32_t smem_u32(const void* p) {
    uint32_t a;
    asm("{ .reg .u64 t; cvta.to.shared.u64 t, %1; cvt.u32.u64 %0, t; }" : "=r"(a) : "l"(p));
    return a;
}
__device__ __forceinline__ void cp16(uint32_t dst, const void* src) {
    asm volatile("cp.async.cg.shared.global [%0], [%1], 16;" :: "r"(dst), "l"(src) : "memory");
}

// ---------------------------------------------------------------------------
// tf32 mma.sync GEMM: C[M,N] = A[M,K] @ B[K,N]. Inputs pre-rounded to tf32.
// 128x128 block tile, 256 threads (8 warps 2x4), warp tile 64x32 = 4x4
// m16n8k8 atoms. K-tile 32, 3-stage cp.async pipeline, 1 barrier/iter.
// smem: A [128][36] row-major (ldmatrix.x4, conflict-free: 36 floats = 9x16B),
//       B [32][136] natural (LDS.32 fragments, banks (8*tig+g)%32 distinct).
// ---------------------------------------------------------------------------
#define GS_A_FLOATS (128 * 36)                    // 4608
#define GS_B_FLOATS (32 * 136)                    // 4352
#define GS_STAGE    (GS_A_FLOATS + GS_B_FLOATS)   // 8960 floats = 35840 B
#define GS_SMEM_BYTES (3 * GS_STAGE * 4)          // 107520 B

__device__ __forceinline__ void issue_stage(uint32_t sb, const float* __restrict__ A,
                                            const float* __restrict__ B,
                                            int tid, int row0, int col0, int k0,
                                            int N, int K) {
#pragma unroll
    for (int i = 0; i < 4; i++) {
        int ff = tid + i * 256;
        int r  = ff >> 3, c4 = (ff & 7) * 4;
        cp16(sb + (r * 36 + c4) * 4, &A[(size_t)(row0 + r) * K + k0 + c4]);
        int k  = ff >> 5, n4 = (ff & 31) * 4;
        cp16(sb + (GS_A_FLOATS + k * 136 + n4) * 4, &B[(size_t)(k0 + k) * N + col0 + n4]);
    }
}

__global__ __launch_bounds__(256, 2) void gemm_mma(const float* __restrict__ A,
                                                   const float* __restrict__ B,
                                                   float* __restrict__ C,
                                                   int M, int N, int K) {
    extern __shared__ __align__(16) float gsm[];
    const uint32_t sb = smem_u32(gsm);
    const int tid  = threadIdx.x;
    const int lane = tid & 31;
    const int wid  = tid >> 5;
    const int wr = wid >> 2, wc = wid & 3;
    const int g  = lane >> 2, tig = lane & 3;
    const int row0 = blockIdx.y * 128;
    const int col0 = blockIdx.x * 128;

    float d[4][4][4] = {};
    const int T = K >> 5;

    issue_stage(sb + 0 * GS_STAGE * 4, A, B, tid, row0, col0, 0, N, K);
    asm volatile("cp.async.commit_group;" ::: "memory");
    issue_stage(sb + 1 * GS_STAGE * 4, A, B, tid, row0, col0, 32, N, K);
    asm volatile("cp.async.commit_group;" ::: "memory");

    // per-thread ldmatrix A base: row = wr*64 + ((lane>>3)&1)*8 + (lane&7),
    // col = ((lane>>4)&1)*4 ; per-ma +16 rows (2304B), per-ks +8 cols (32B)
    const uint32_t a_base = sb + ((wr * 64 + ((lane >> 3) & 1) * 8 + (lane & 7)) * 36
                                  + ((lane >> 4) & 1) * 4) * 4;

    for (int t = 0; t < T; t++) {
        const int s = t % 3;
        asm volatile("cp.async.wait_group 1;" ::: "memory");
        __syncthreads();

        const uint32_t aS = a_base + s * GS_STAGE * 4;
        const uint32_t* sBu = (const uint32_t*)(gsm + s * GS_STAGE + GS_A_FLOATS);
        const int bcol = wc * 32 + g;

#pragma unroll
        for (int ks = 0; ks < 4; ks++) {
            uint32_t af[4][4], bf[4][2];
#pragma unroll
            for (int ma = 0; ma < 4; ma++)
                asm volatile("ldmatrix.sync.aligned.m8n8.x4.shared.b16 {%0,%1,%2,%3}, [%4];"
                             : "=r"(af[ma][0]), "=r"(af[ma][1]),
                               "=r"(af[ma][2]), "=r"(af[ma][3])
                             : "r"(aS + ma * 2304 + ks * 32));
#pragma unroll
            for (int na = 0; na < 4; na++) {
                bf[na][0] = sBu[(ks * 8 + tig) * 136 + bcol + na * 8];
                bf[na][1] = sBu[(ks * 8 + tig + 4) * 136 + bcol + na * 8];
            }
#pragma unroll
            for (int ma = 0; ma < 4; ma++)
#pragma unroll
                for (int na = 0; na < 4; na++)
                    asm volatile(
                        "mma.sync.aligned.m16n8k8.row.col.f32.tf32.tf32.f32 "
                        "{%0,%1,%2,%3}, {%4,%5,%6,%7}, {%8,%9}, {%0,%1,%2,%3};"
                        : "+f"(d[ma][na][0]), "+f"(d[ma][na][1]),
                          "+f"(d[ma][na][2]), "+f"(d[ma][na][3])
                        : "r"(af[ma][0]), "r"(af[ma][1]), "r"(af[ma][2]), "r"(af[ma][3]),
                          "r"(bf[na][0]), "r"(bf[na][1]));
        }

        if (t + 2 < T)
            issue_stage(sb + ((t + 2) % 3) * GS_STAGE * 4, A, B, tid,
                        row0, col0, (t + 2) * 32, N, K);
        asm volatile("cp.async.commit_group;" ::: "memory");
    }

    // Epilogue: fragment (c0,c1)@(row g, col tig*2), (c2,c3)@(row g+8)
#pragma unroll
    for (int ma = 0; ma < 4; ma++)
#pragma unroll
        for (int na = 0; na < 4; na++) {
            const int r = row0 + wr * 64 + ma * 16 + g;
            const int c = col0 + wc * 32 + na * 8 + tig * 2;
            *(float2*)&C[(size_t)r * N + c]       = make_float2(d[ma][na][0], d[ma][na][1]);
            *(float2*)&C[(size_t)(r + 8) * N + c] = make_float2(d[ma][na][2], d[ma][na][3]);
        }
}

// ---------------------------------------------------------------------------
// Elementwise tf32 pre-round (bandwidth-bound)
// ---------------------------------------------------------------------------
__global__ void round_tf32_kernel(const float* __restrict__ in, float* __restrict__ out,
                                  int n4) {
    int i = blockIdx.x * blockDim.x + threadIdx.x;
    if (i < n4) {
        float4 v = ((const float4*)in)[i];
        v.x = to_tf32(v.x); v.y = to_tf32(v.y);
        v.z = to_tf32(v.z); v.w = to_tf32(v.w);
        ((float4*)out)[i] = v;
    }
}

// ---------------------------------------------------------------------------
// Causal flash attention, fp32 SIMT, outer-product register tiling (R2).
// Epilogue rounds output to tf32 (pre-rounds the out-proj A operand).
// ---------------------------------------------------------------------------
#define FA_QT 128
#define FA_KT 64
#define QS_STRIDE 132
#define KS_STRIDE 68
#define PS_STRIDE 132
#define FA_SMEM_FLOATS (64*QS_STRIDE + 64*KS_STRIDE + 64*KS_STRIDE + 64*PS_STRIDE)

__global__ __launch_bounds__(256, 2) void flash_attn_kernel() {
    extern __shared__ float sm[];
    float* Qs = sm;
    float* Ks = Qs + 64 * QS_STRIDE;
    float* Vs = Ks + 64 * KS_STRIDE;
    float* Ps = Vs + 64 * KS_STRIDE;

    const int tid = threadIdx.x;
    const int qt  = (gridDim.x - 1) - blockIdx.x;
    const int bh  = blockIdx.y;
    const int b   = bh >> 4;
    const int h   = bh & 15;

    const float* base = g_qkv + (size_t)b * T_SEQ * QKV_LD + h * HEAD_DIM;
    const float* Qg = base;
    const float* Kg = base + D_MODEL;
    const float* Vg = base + 2 * D_MODEL;

    const int tq = tid >> 4;
    const int tk = tid & 15;
    const int q0 = qt * FA_QT;

#pragma unroll
    for (int i = 0; i < 8; i++) {
        int ff = tid + i * 256;
        int r  = ff >> 4;
        int d4 = (ff & 15) * 4;
        float4 v = *(const float4*)&Qg[(size_t)(q0 + r) * QKV_LD + d4];
        Qs[(d4 + 0) * QS_STRIDE + r] = v.x;
        Qs[(d4 + 1) * QS_STRIDE + r] = v.y;
        Qs[(d4 + 2) * QS_STRIDE + r] = v.z;
        Qs[(d4 + 3) * QS_STRIDE + r] = v.w;
    }

    const float NEG_INF = __int_as_float(0xff800000u);
    const float scale = 0.125f;
    float m[8], l[8], o[8][4];
#pragma unroll
    for (int i = 0; i < 8; i++) {
        m[i] = NEG_INF; l[i] = 0.f;
#pragma unroll
        for (int j = 0; j < 4; j++) o[i][j] = 0.f;
    }

    const int nkt = 2 * qt + 2;
    for (int kt = 0; kt < nkt; kt++) {
        __syncthreads();
#pragma unroll
        for (int i = 0; i < 4; i++) {
            int ff = tid + i * 256;
            int r  = ff >> 4;
            int d4 = (ff & 15) * 4;
            float4 kv = *(const float4*)&Kg[(size_t)(kt * FA_KT + r) * QKV_LD + d4];
            Ks[(d4 + 0) * KS_STRIDE + r] = kv.x;
            Ks[(d4 + 1) * KS_STRIDE + r] = kv.y;
            Ks[(d4 + 2) * KS_STRIDE + r] = kv.z;
            Ks[(d4 + 3) * KS_STRIDE + r] = kv.w;
            float4 vv = *(const float4*)&Vg[(size_t)(kt * FA_KT + r) * QKV_LD + d4];
            *(float4*)&Vs[r * KS_STRIDE + d4] = vv;
        }
        __syncthreads();

        float s[8][4];
#pragma unroll
        for (int i = 0; i < 8; i++)
#pragma unroll
            for (int j = 0; j < 4; j++) s[i][j] = 0.f;

#pragma unroll 8
        for (int d = 0; d < 64; d++) {
            float qv[8], kv[4];
            *(float4*)&qv[0] = *(const float4*)&Qs[d * QS_STRIDE + tq * 8];
            *(float4*)&qv[4] = *(const float4*)&Qs[d * QS_STRIDE + tq * 8 + 4];
            *(float4*)&kv[0] = *(const float4*)&Ks[d * KS_STRIDE + tk * 4];
#pragma unroll
            for (int i = 0; i < 8; i++)
#pragma unroll
                for (int j = 0; j < 4; j++) s[i][j] = fmaf(qv[i], kv[j], s[i][j]);
        }

        const bool diag = (kt >= 2 * qt);
#pragma unroll
        for (int i = 0; i < 8; i++) {
            const int qg = q0 + tq * 8 + i;
#pragma unroll
            for (int j = 0; j < 4; j++) {
                s[i][j] *= scale;
                if (diag) {
                    int kg = kt * FA_KT + tk * 4 + j;
                    if (kg > qg) s[i][j] = NEG_INF;
                }
            }
        }

#pragma unroll
        for (int i = 0; i < 8; i++) {
            float tm = fmaxf(fmaxf(s[i][0], s[i][1]), fmaxf(s[i][2], s[i][3]));
            tm = fmaxf(tm, __shfl_xor_sync(0xffffffffu, tm, 1, 16));
            tm = fmaxf(tm, __shfl_xor_sync(0xffffffffu, tm, 2, 16));
            tm = fmaxf(tm, __shfl_xor_sync(0xffffffffu, tm, 4, 16));
            tm = fmaxf(tm, __shfl_xor_sync(0xffffffffu, tm, 8, 16));
            float m_new = fmaxf(m[i], tm);
            float alpha = __expf(m[i] - m_new);
            float psum = 0.f;
#pragma unroll
            for (int j = 0; j < 4; j++) {
                float p = __expf(s[i][j] - m_new);
                s[i][j] = p;
                psum += p;
            }
            psum += __shfl_xor_sync(0xffffffffu, psum, 1, 16);
            psum += __shfl_xor_sync(0xffffffffu, psum, 2, 16);
            psum += __shfl_xor_sync(0xffffffffu, psum, 4, 16);
            psum += __shfl_xor_sync(0xffffffffu, psum, 8, 16);
            l[i] = l[i] * alpha + psum;
            m[i] = m_new;
#pragma unroll
            for (int j = 0; j < 4; j++) o[i][j] *= alpha;
        }

#pragma unroll
        for (int j = 0; j < 4; j++)
#pragma unroll
            for (int i = 0; i < 8; i++)
                Ps[(tk * 4 + j) * PS_STRIDE + tq * 8 + i] = s[i][j];
        __syncthreads();

#pragma unroll 8
        for (int k = 0; k < 64; k++) {
            float pv[8], vv[4];
            *(float4*)&pv[0] = *(const float4*)&Ps[k * PS_STRIDE + tq * 8];
            *(float4*)&pv[4] = *(const float4*)&Ps[k * PS_STRIDE + tq * 8 + 4];
            *(float4*)&vv[0] = *(const float4*)&Vs[k * KS_STRIDE + tk * 4];
#pragma unroll
            for (int i = 0; i < 8; i++)
#pragma unroll
                for (int j = 0; j < 4; j++) o[i][j] = fmaf(pv[i], vv[j], o[i][j]);
        }
    }

#pragma unroll
    for (int i = 0; i < 8; i++) {
        float inv = 1.f / l[i];
        const int qg = q0 + tq * 8 + i;
        float4 c = make_float4(to_tf32(o[i][0] * inv), to_tf32(o[i][1] * inv),
                               to_tf32(o[i][2] * inv), to_tf32(o[i][3] * inv));
        *(float4*)&g_attn[(size_t)(b * T_SEQ + qg) * D_MODEL + h * HEAD_DIM + tk * 4] = c;
    }
}

// ---------------------------------------------------------------------------
// Launch
// ---------------------------------------------------------------------------
extern "C" void kernel_launch(void* const* d_in, const int* in_sizes, int n_in,
                              void* d_out, int out_size) {
    const float* x     = (const float*)d_in[0];   // [2,2048,1024]
    const float* w_qkv = (const float*)d_in[1];   // [1024,3072]
    const float* w_out = (const float*)d_in[2];   // [1024,1024]
    float* out = (float*)d_out;                   // [2,2048,1024]

    void *qkv_p, *attn_p, *xr_p, *wqkv_p, *wout_p;
    cudaGetSymbolAddress(&qkv_p,  g_qkv);
    cudaGetSymbolAddress(&attn_p, g_attn);
    cudaGetSymbolAddress(&xr_p,   g_xr);
    cudaGetSymbolAddress(&wqkv_p, g_wqkv_r);
    cudaGetSymbolAddress(&wout_p, g_wout_r);

    const int fa_smem = FA_SMEM_FLOATS * (int)sizeof(float);   // 102400 B
    cudaFuncSetAttribute(flash_attn_kernel,
                         cudaFuncAttributeMaxDynamicSharedMemorySize, fa_smem);
    cudaFuncSetAttribute(gemm_mma,
                         cudaFuncAttributeMaxDynamicSharedMemorySize, GS_SMEM_BYTES);

    // 0) pre-round inputs to tf32
    {
        int n4 = M_TOTAL * D_MODEL / 4;
        round_tf32_kernel<<<(n4 + 255) / 256, 256>>>(x, (float*)xr_p, n4);
        n4 = D_MODEL * QKV_LD / 4;
        round_tf32_kernel<<<(n4 + 255) / 256, 256>>>(w_qkv, (float*)wqkv_p, n4);
        n4 = D_MODEL * D_MODEL / 4;
        round_tf32_kernel<<<(n4 + 255) / 256, 256>>>(w_out, (float*)wout_p, n4);
    }

    // 1) QKV projection: [4096,1024] @ [1024,3072]
    gemm_mma<<<dim3(QKV_LD / 128, M_TOTAL / 128), 256, GS_SMEM_BYTES>>>(
        (const float*)xr_p, (const float*)wqkv_p, (float*)qkv_p,
        M_TOTAL, QKV_LD, D_MODEL);

    // 2) causal flash attention per (b,h)
    flash_attn_kernel<<<dim3(T_SEQ / FA_QT, BATCH * N_HEADS), 256, fa_smem>>>();

    // 3) output projection: [4096,1024] @ [1024,1024]
    gemm_mma<<<dim3(D_MODEL / 128, M_TOTAL / 128), 256, GS_SMEM_BYTES>>>(
        (const float*)attn_p, (const float*)wout_p, out,
        M_TOTAL, D_MODEL, D_MODEL);
}

// round 6
// speedup vs baseline: 3.4788x; 1.9530x over previous
#include <cuda_runtime.h>
#include <math.h>
#include <stdint.h>

// Problem constants
#define BATCH    2
#define T_SEQ    2048
#define D_MODEL  1024
#define N_HEADS  16
#define HEAD_DIM 64
#define M_TOTAL  (BATCH * T_SEQ)          // 4096 rows
#define QKV_LD   (3 * D_MODEL)            // 3072

// Scratch (allocation-free rule: __device__ globals)
__device__ float g_qkv   [M_TOTAL * QKV_LD];    // [4096, 3072] tf32-rounded (gemm<ROUND>)
__device__ float g_attn  [M_TOTAL * D_MODEL];   // [4096, 1024] tf32-rounded by flash
__device__ float g_xr    [M_TOTAL * D_MODEL];   // tf32-rounded x
__device__ float g_wqkv_r[D_MODEL * QKV_LD];    // tf32-rounded w_qkv
__device__ float g_wout_r[D_MODEL * D_MODEL];   // tf32-rounded w_out

__device__ __forceinline__ float to_tf32(float x) {
    float y;
    asm("cvt.rna.tf32.f32 %0, %1;" : "=f"(y) : "f"(x));
    return y;
}
__device__ __forceinline__ uint32_t smem_u32(const void* p) {
    uint32_t a;
    asm("{ .reg .u64 t; cvta.to.shared.u64 t, %1; cvt.u32.u64 %0, t; }" : "=r"(a) : "l"(p));
    return a;
}
__device__ __forceinline__ void cp16(uint32_t dst, const void* src) {
    asm volatile("cp.async.cg.shared.global [%0], [%1], 16;" :: "r"(dst), "l"(src) : "memory");
}
#define MMA_TF32(D, A, B) \
    asm volatile("mma.sync.aligned.m16n8k8.row.col.f32.tf32.tf32.f32 " \
                 "{%0,%1,%2,%3}, {%4,%5,%6,%7}, {%8,%9}, {%0,%1,%2,%3};" \
                 : "+f"((D)[0]), "+f"((D)[1]), "+f"((D)[2]), "+f"((D)[3]) \
                 : "r"((A)[0]), "r"((A)[1]), "r"((A)[2]), "r"((A)[3]), \
                   "r"((B)[0]), "r"((B)[1]))
#define LDMATRIX_X4(R, ADDR) \
    asm volatile("ldmatrix.sync.aligned.m8n8.x4.shared.b16 {%0,%1,%2,%3}, [%4];" \
                 : "=r"((R)[0]), "=r"((R)[1]), "=r"((R)[2]), "=r"((R)[3]) : "r"(ADDR))

// ---------------------------------------------------------------------------
// tf32 mma.sync GEMM (R5, + optional tf32 rounding of output).
// ---------------------------------------------------------------------------
#define GS_A_FLOATS (128 * 36)
#define GS_B_FLOATS (32 * 136)
#define GS_STAGE    (GS_A_FLOATS + GS_B_FLOATS)   // 8960 floats
#define GS_SMEM_BYTES (3 * GS_STAGE * 4)          // 107520 B

__device__ __forceinline__ void issue_stage(uint32_t sb, const float* __restrict__ A,
                                            const float* __restrict__ B,
                                            int tid, int row0, int col0, int k0,
                                            int N, int K) {
#pragma unroll
    for (int i = 0; i < 4; i++) {
        int ff = tid + i * 256;
        int r  = ff >> 3, c4 = (ff & 7) * 4;
        cp16(sb + (r * 36 + c4) * 4, &A[(size_t)(row0 + r) * K + k0 + c4]);
        int k  = ff >> 5, n4 = (ff & 31) * 4;
        cp16(sb + (GS_A_FLOATS + k * 136 + n4) * 4, &B[(size_t)(k0 + k) * N + col0 + n4]);
    }
}

template <bool ROUND>
__global__ __launch_bounds__(256, 2) void gemm_mma(const float* __restrict__ A,
                                                   const float* __restrict__ B,
                                                   float* __restrict__ C,
                                                   int M, int N, int K) {
    extern __shared__ __align__(16) float gsm[];
    const uint32_t sb = smem_u32(gsm);
    const int tid  = threadIdx.x;
    const int lane = tid & 31;
    const int wid  = tid >> 5;
    const int wr = wid >> 2, wc = wid & 3;
    const int g  = lane >> 2, tig = lane & 3;
    const int row0 = blockIdx.y * 128;
    const int col0 = blockIdx.x * 128;

    float d[4][4][4] = {};
    const int T = K >> 5;

    issue_stage(sb + 0 * GS_STAGE * 4, A, B, tid, row0, col0, 0, N, K);
    asm volatile("cp.async.commit_group;" ::: "memory");
    issue_stage(sb + 1 * GS_STAGE * 4, A, B, tid, row0, col0, 32, N, K);
    asm volatile("cp.async.commit_group;" ::: "memory");

    const uint32_t a_base = sb + ((wr * 64 + ((lane >> 3) & 1) * 8 + (lane & 7)) * 36
                                  + ((lane >> 4) & 1) * 4) * 4;

    for (int t = 0; t < T; t++) {
        const int s = t % 3;
        asm volatile("cp.async.wait_group 1;" ::: "memory");
        __syncthreads();

        const uint32_t aS = a_base + s * GS_STAGE * 4;
        const uint32_t* sBu = (const uint32_t*)(gsm + s * GS_STAGE + GS_A_FLOATS);
        const int bcol = wc * 32 + g;

#pragma unroll
        for (int ks = 0; ks < 4; ks++) {
            uint32_t af[4][4], bf[4][2];
#pragma unroll
            for (int ma = 0; ma < 4; ma++)
                LDMATRIX_X4(af[ma], aS + ma * 2304 + ks * 32);
#pragma unroll
            for (int na = 0; na < 4; na++) {
                bf[na][0] = sBu[(ks * 8 + tig) * 136 + bcol + na * 8];
                bf[na][1] = sBu[(ks * 8 + tig + 4) * 136 + bcol + na * 8];
            }
#pragma unroll
            for (int ma = 0; ma < 4; ma++)
#pragma unroll
                for (int na = 0; na < 4; na++)
                    MMA_TF32(d[ma][na], af[ma], bf[na]);
        }

        if (t + 2 < T)
            issue_stage(sb + ((t + 2) % 3) * GS_STAGE * 4, A, B, tid,
                        row0, col0, (t + 2) * 32, N, K);
        asm volatile("cp.async.commit_group;" ::: "memory");
    }

#pragma unroll
    for (int ma = 0; ma < 4; ma++)
#pragma unroll
        for (int na = 0; na < 4; na++) {
            const int r = row0 + wr * 64 + ma * 16 + g;
            const int c = col0 + wc * 32 + na * 8 + tig * 2;
            float4 v = make_float4(d[ma][na][0], d[ma][na][1], d[ma][na][2], d[ma][na][3]);
            if (ROUND) {
                v.x = to_tf32(v.x); v.y = to_tf32(v.y);
                v.z = to_tf32(v.z); v.w = to_tf32(v.w);
            }
            *(float2*)&C[(size_t)r * N + c]       = make_float2(v.x, v.y);
            *(float2*)&C[(size_t)(r + 8) * N + c] = make_float2(v.z, v.w);
        }
}

// ---------------------------------------------------------------------------
// Elementwise tf32 pre-round
// ---------------------------------------------------------------------------
__global__ void round_tf32_kernel(const float* __restrict__ in, float* __restrict__ out,
                                  int n4) {
    int i = blockIdx.x * blockDim.x + threadIdx.x;
    if (i < n4) {
        float4 v = ((const float4*)in)[i];
        v.x = to_tf32(v.x); v.y = to_tf32(v.y);
        v.z = to_tf32(v.z); v.w = to_tf32(v.w);
        ((float4*)out)[i] = v;
    }
}

// ---------------------------------------------------------------------------
// Causal flash attention on tensor cores (tf32 mma.sync).
// grid = (16, 32), 256 threads (8 warps). Q tile 128, key tiles 64.
// Warp w owns q rows [16w, 16w+16): 1 m-atom x 8 n-atoms per mma stage.
// S = Q K^T : A = Q[q][d] (ldmatrix, stride 68), B = K[key][d] NATURAL
//   (row.col mma: B[k=d][n=key] == K[key][d]) -> cp.async, no transpose.
// PV: A = P[q][key] (smem round-trip, ldmatrix), B = V[key][d] natural.
// Bank-exact: K stride 68 (banks 4g+tig), V stride 72 (banks 8tig+g),
// Q/P stride 68 = 17x16B (ldmatrix conflict-free).
// ---------------------------------------------------------------------------
#define FQ_STRIDE 68
#define FK_STRIDE 68
#define FV_STRIDE 72
#define FP_STRIDE 68
#define F_QS 0
#define F_PS (128 * FQ_STRIDE)
#define F_KS (F_PS + 128 * FP_STRIDE)
#define F_VS (F_KS + 64 * FK_STRIDE)
#define F_SMEM_FLOATS (F_VS + 64 * FV_STRIDE)       // 26368 floats = 105472 B

__global__ __launch_bounds__(256, 2) void flash_mma_kernel() {
    extern __shared__ __align__(16) float fsm[];
    const uint32_t sb = smem_u32(fsm);
    const int tid  = threadIdx.x;
    const int lane = tid & 31;
    const int wid  = tid >> 5;
    const int g    = lane >> 2;
    const int tig  = lane & 3;

    const int qt = (gridDim.x - 1) - blockIdx.x;     // reversed: heavy first
    const int bh = blockIdx.y;
    const int b  = bh >> 4;
    const int h  = bh & 15;
    const int q0 = qt * 128;

    const float* base = g_qkv + (size_t)b * T_SEQ * QKV_LD + h * HEAD_DIM;
    const float* Qg = base;
    const float* Kg = base + D_MODEL;
    const float* Vg = base + 2 * D_MODEL;

    // ---- Q tile via cp.async: [128][64] -> stride 68 ----
#pragma unroll
    for (int i = 0; i < 8; i++) {
        int ff = tid + i * 256;
        int r  = ff >> 4;
        int d4 = (ff & 15) * 4;
        cp16(sb + (F_QS + r * FQ_STRIDE + d4) * 4, &Qg[(size_t)(q0 + r) * QKV_LD + d4]);
    }
    asm volatile("cp.async.commit_group;" ::: "memory");

    // ldmatrix base (rows within this warp's 16-row tile)
    const int lm_row = wid * 16 + ((lane >> 3) & 1) * 8 + (lane & 7);
    const int lm_col = ((lane >> 4) & 1) * 4;
    const uint32_t q_lm = sb + (F_QS + lm_row * FQ_STRIDE + lm_col) * 4;
    const uint32_t p_lm = sb + (F_PS + lm_row * FP_STRIDE + lm_col) * 4;

    const float NEG_INF = __int_as_float(0xff800000u);
    const float scale = 0.125f;
    float o[8][4] = {};
    float m0 = NEG_INF, m1 = NEG_INF, l0 = 0.f, l1 = 0.f;

    const int nkt = 2 * qt + 2;
    for (int kt = 0; kt < nkt; kt++) {
        __syncthreads();            // prev PV done reading Vs/Ps; Ks/Vs free
        // ---- K,V tiles via cp.async, natural layout ----
#pragma unroll
        for (int i = 0; i < 4; i++) {
            int ff = tid + i * 256;
            int r  = ff >> 4;
            int d4 = (ff & 15) * 4;
            const size_t grow = (size_t)(kt * 64 + r) * QKV_LD + d4;
            cp16(sb + (F_KS + r * FK_STRIDE + d4) * 4, &Kg[grow]);
            cp16(sb + (F_VS + r * FV_STRIDE + d4) * 4, &Vg[grow]);
        }
        asm volatile("cp.async.commit_group;" ::: "memory");
        asm volatile("cp.async.wait_group 0;" ::: "memory");
        __syncthreads();

        // ---- S = Q K^T : 8 ks x 8 na ----
        float s[8][4] = {};
#pragma unroll
        for (int ks = 0; ks < 8; ks++) {
            uint32_t af[4];
            LDMATRIX_X4(af, q_lm + ks * 32);
#pragma unroll
            for (int na = 0; na < 8; na++) {
                uint32_t bf[2];
                bf[0] = __float_as_uint(fsm[F_KS + (na * 8 + g) * FK_STRIDE + ks * 8 + tig]);
                bf[1] = __float_as_uint(fsm[F_KS + (na * 8 + g) * FK_STRIDE + ks * 8 + tig + 4]);
                MMA_TF32(s[na], af, bf);
            }
        }

        // ---- scale + causal mask ----
        const bool diag = (kt >= 2 * qt);
        const int qr0 = q0 + wid * 16 + g;
        const int qr1 = qr0 + 8;
#pragma unroll
        for (int na = 0; na < 8; na++) {
            const int kg = kt * 64 + na * 8 + 2 * tig;
            s[na][0] *= scale; s[na][1] *= scale;
            s[na][2] *= scale; s[na][3] *= scale;
            if (diag) {
                if (kg     > qr0) s[na][0] = NEG_INF;
                if (kg + 1 > qr0) s[na][1] = NEG_INF;
                if (kg     > qr1) s[na][2] = NEG_INF;
                if (kg + 1 > qr1) s[na][3] = NEG_INF;
            }
        }

        // ---- online softmax (rows g / g+8; reduce across quad tig) ----
        float mx0 = NEG_INF, mx1 = NEG_INF;
#pragma unroll
        for (int na = 0; na < 8; na++) {
            mx0 = fmaxf(mx0, fmaxf(s[na][0], s[na][1]));
            mx1 = fmaxf(mx1, fmaxf(s[na][2], s[na][3]));
        }
        mx0 = fmaxf(mx0, __shfl_xor_sync(0xffffffffu, mx0, 1));
        mx0 = fmaxf(mx0, __shfl_xor_sync(0xffffffffu, mx0, 2));
        mx1 = fmaxf(mx1, __shfl_xor_sync(0xffffffffu, mx1, 1));
        mx1 = fmaxf(mx1, __shfl_xor_sync(0xffffffffu, mx1, 2));
        const float mn0 = fmaxf(m0, mx0);
        const float mn1 = fmaxf(m1, mx1);
        const float a0 = __expf(m0 - mn0);
        const float a1 = __expf(m1 - mn1);
        float sum0 = 0.f, sum1 = 0.f;
#pragma unroll
        for (int na = 0; na < 8; na++) {
            s[na][0] = __expf(s[na][0] - mn0);
            s[na][1] = __expf(s[na][1] - mn0);
            s[na][2] = __expf(s[na][2] - mn1);
            s[na][3] = __expf(s[na][3] - mn1);
            sum0 += s[na][0] + s[na][1];
            sum1 += s[na][2] + s[na][3];
        }
        sum0 += __shfl_xor_sync(0xffffffffu, sum0, 1);
        sum0 += __shfl_xor_sync(0xffffffffu, sum0, 2);
        sum1 += __shfl_xor_sync(0xffffffffu, sum1, 1);
        sum1 += __shfl_xor_sync(0xffffffffu, sum1, 2);
        l0 = l0 * a0 + sum0;  m0 = mn0;
        l1 = l1 * a1 + sum1;  m1 = mn1;
#pragma unroll
        for (int na = 0; na < 8; na++) {
            o[na][0] *= a0; o[na][1] *= a0;
            o[na][2] *= a1; o[na][3] *= a1;
        }

        // ---- write P (tf32-rounded) to smem: Ps[q][key] ----
        {
            const int pr0 = wid * 16 + g;
            const int kc  = 2 * tig;
#pragma unroll
            for (int na = 0; na < 8; na++) {
                *(float2*)&fsm[F_PS + pr0 * FP_STRIDE + na * 8 + kc] =
                    make_float2(to_tf32(s[na][0]), to_tf32(s[na][1]));
                *(float2*)&fsm[F_PS + (pr0 + 8) * FP_STRIDE + na * 8 + kc] =
                    make_float2(to_tf32(s[na][2]), to_tf32(s[na][3]));
            }
        }
        __syncthreads();

        // ---- O += P V : 8 ks(key) x 8 na(d) ----
#pragma unroll
        for (int ks = 0; ks < 8; ks++) {
            uint32_t af[4];
            LDMATRIX_X4(af, p_lm + ks * 32);
#pragma unroll
            for (int na = 0; na < 8; na++) {
                uint32_t bf[2];
                bf[0] = __float_as_uint(fsm[F_VS + (ks * 8 + tig) * FV_STRIDE + na * 8 + g]);
                bf[1] = __float_as_uint(fsm[F_VS + (ks * 8 + tig + 4) * FV_STRIDE + na * 8 + g]);
                MMA_TF32(o[na], af, bf);
            }
        }
    }

    // ---- epilogue: /l, tf32-round (A operand of out-proj), store ----
    const float i0 = 1.f / l0;
    const float i1 = 1.f / l1;
    const int r0 = q0 + wid * 16 + g;
    float* out0 = &g_attn[(size_t)(b * T_SEQ + r0) * D_MODEL + h * HEAD_DIM + 2 * tig];
    float* out1 = &g_attn[(size_t)(b * T_SEQ + r0 + 8) * D_MODEL + h * HEAD_DIM + 2 * tig];
#pragma unroll
    for (int na = 0; na < 8; na++) {
        *(float2*)&out0[na * 8] = make_float2(to_tf32(o[na][0] * i0), to_tf32(o[na][1] * i0));
        *(float2*)&out1[na * 8] = make_float2(to_tf32(o[na][2] * i1), to_tf32(o[na][3] * i1));
    }
}

// ---------------------------------------------------------------------------
// Launch
// ---------------------------------------------------------------------------
extern "C" void kernel_launch(void* const* d_in, const int* in_sizes, int n_in,
                              void* d_out, int out_size) {
    const float* x     = (const float*)d_in[0];   // [2,2048,1024]
    const float* w_qkv = (const float*)d_in[1];   // [1024,3072]
    const float* w_out = (const float*)d_in[2];   // [1024,1024]
    float* out = (float*)d_out;                   // [2,2048,1024]

    void *qkv_p, *attn_p, *xr_p, *wqkv_p, *wout_p;
    cudaGetSymbolAddress(&qkv_p,  g_qkv);
    cudaGetSymbolAddress(&attn_p, g_attn);
    cudaGetSymbolAddress(&xr_p,   g_xr);
    cudaGetSymbolAddress(&wqkv_p, g_wqkv_r);
    cudaGetSymbolAddress(&wout_p, g_wout_r);

    const int fa_smem = F_SMEM_FLOATS * (int)sizeof(float);    // 105472 B
    cudaFuncSetAttribute(flash_mma_kernel,
                         cudaFuncAttributeMaxDynamicSharedMemorySize, fa_smem);
    cudaFuncSetAttribute(gemm_mma<true>,
                         cudaFuncAttributeMaxDynamicSharedMemorySize, GS_SMEM_BYTES);
    cudaFuncSetAttribute(gemm_mma<false>,
                         cudaFuncAttributeMaxDynamicSharedMemorySize, GS_SMEM_BYTES);

    // 0) pre-round inputs to tf32
    {
        int n4 = M_TOTAL * D_MODEL / 4;
        round_tf32_kernel<<<(n4 + 255) / 256, 256>>>(x, (float*)xr_p, n4);
        n4 = D_MODEL * QKV_LD / 4;
        round_tf32_kernel<<<(n4 + 255) / 256, 256>>>(w_qkv, (float*)wqkv_p, n4);
        n4 = D_MODEL * D_MODEL / 4;
        round_tf32_kernel<<<(n4 + 255) / 256, 256>>>(w_out, (float*)wout_p, n4);
    }

    // 1) QKV projection (output tf32-rounded for flash's tensor-core consumption)
    gemm_mma<true><<<dim3(QKV_LD / 128, M_TOTAL / 128), 256, GS_SMEM_BYTES>>>(
        (const float*)xr_p, (const float*)wqkv_p, (float*)qkv_p,
        M_TOTAL, QKV_LD, D_MODEL);

    // 2) causal flash attention (tensor cores)
    flash_mma_kernel<<<dim3(T_SEQ / 128, BATCH * N_HEADS), 256, fa_smem>>>();

    // 3) output projection
    gemm_mma<false><<<dim3(D_MODEL / 128, M_TOTAL / 128), 256, GS_SMEM_BYTES>>>(
        (const float*)attn_p, (const float*)wout_p, out,
        M_TOTAL, D_MODEL, D_MODEL);
}

// round 7
// speedup vs baseline: 3.5801x; 1.0291x over previous
#include <cuda_runtime.h>
#include <math.h>
#include <stdint.h>

// Problem constants
#define BATCH    2
#define T_SEQ    2048
#define D_MODEL  1024
#define N_HEADS  16
#define HEAD_DIM 64
#define M_TOTAL  (BATCH * T_SEQ)          // 4096 rows
#define QKV_LD   (3 * D_MODEL)            // 3072

// Scratch (allocation-free rule: __device__ globals)
__device__ float g_qkv   [M_TOTAL * QKV_LD];    // [4096, 3072] tf32-rounded (gemm<ROUND>)
__device__ float g_attn  [M_TOTAL * D_MODEL];   // [4096, 1024] tf32-rounded by flash
__device__ float g_xr    [M_TOTAL * D_MODEL];   // tf32-rounded x
__device__ float g_wqkv_r[D_MODEL * QKV_LD];    // tf32-rounded w_qkv
__device__ float g_wout_r[D_MODEL * D_MODEL];   // tf32-rounded w_out

__device__ __forceinline__ float to_tf32(float x) {
    float y;
    asm("cvt.rna.tf32.f32 %0, %1;" : "=f"(y) : "f"(x));
    return y;
}
__device__ __forceinline__ uint32_t smem_u32(const void* p) {
    uint32_t a;
    asm("{ .reg .u64 t; cvta.to.shared.u64 t, %1; cvt.u32.u64 %0, t; }" : "=r"(a) : "l"(p));
    return a;
}
__device__ __forceinline__ void cp16(uint32_t dst, const void* src) {
    asm volatile("cp.async.cg.shared.global [%0], [%1], 16;" :: "r"(dst), "l"(src) : "memory");
}
#define MMA_TF32(D, A, B) \
    asm volatile("mma.sync.aligned.m16n8k8.row.col.f32.tf32.tf32.f32 " \
                 "{%0,%1,%2,%3}, {%4,%5,%6,%7}, {%8,%9}, {%0,%1,%2,%3};" \
                 : "+f"((D)[0]), "+f"((D)[1]), "+f"((D)[2]), "+f"((D)[3]) \
                 : "r"((A)[0]), "r"((A)[1]), "r"((A)[2]), "r"((A)[3]), \
                   "r"((B)[0]), "r"((B)[1]))
#define LDMATRIX_X4(R, ADDR) \
    asm volatile("ldmatrix.sync.aligned.m8n8.x4.shared.b16 {%0,%1,%2,%3}, [%4];" \
                 : "=r"((R)[0]), "=r"((R)[1]), "=r"((R)[2]), "=r"((R)[3]) : "r"(ADDR))

// ---------------------------------------------------------------------------
// tf32 mma.sync GEMM (R5/R6, validated; optional tf32 rounding of output).
// ---------------------------------------------------------------------------
#define GS_A_FLOATS (128 * 36)
#define GS_B_FLOATS (32 * 136)
#define GS_STAGE    (GS_A_FLOATS + GS_B_FLOATS)   // 8960 floats
#define GS_SMEM_BYTES (3 * GS_STAGE * 4)          // 107520 B

__device__ __forceinline__ void issue_stage(uint32_t sb, const float* __restrict__ A,
                                            const float* __restrict__ B,
                                            int tid, int row0, int col0, int k0,
                                            int N, int K) {
#pragma unroll
    for (int i = 0; i < 4; i++) {
        int ff = tid + i * 256;
        int r  = ff >> 3, c4 = (ff & 7) * 4;
        cp16(sb + (r * 36 + c4) * 4, &A[(size_t)(row0 + r) * K + k0 + c4]);
        int k  = ff >> 5, n4 = (ff & 31) * 4;
        cp16(sb + (GS_A_FLOATS + k * 136 + n4) * 4, &B[(size_t)(k0 + k) * N + col0 + n4]);
    }
}

template <bool ROUND>
__global__ __launch_bounds__(256, 2) void gemm_mma(const float* __restrict__ A,
                                                   const float* __restrict__ B,
                                                   float* __restrict__ C,
                                                   int M, int N, int K) {
    extern __shared__ __align__(16) float gsm[];
    const uint32_t sb = smem_u32(gsm);
    const int tid  = threadIdx.x;
    const int lane = tid & 31;
    const int wid  = tid >> 5;
    const int wr = wid >> 2, wc = wid & 3;
    const int g  = lane >> 2, tig = lane & 3;
    const int row0 = blockIdx.y * 128;
    const int col0 = blockIdx.x * 128;

    float d[4][4][4] = {};
    const int T = K >> 5;

    issue_stage(sb + 0 * GS_STAGE * 4, A, B, tid, row0, col0, 0, N, K);
    asm volatile("cp.async.commit_group;" ::: "memory");
    issue_stage(sb + 1 * GS_STAGE * 4, A, B, tid, row0, col0, 32, N, K);
    asm volatile("cp.async.commit_group;" ::: "memory");

    const uint32_t a_base = sb + ((wr * 64 + ((lane >> 3) & 1) * 8 + (lane & 7)) * 36
                                  + ((lane >> 4) & 1) * 4) * 4;

    for (int t = 0; t < T; t++) {
        const int s = t % 3;
        asm volatile("cp.async.wait_group 1;" ::: "memory");
        __syncthreads();

        const uint32_t aS = a_base + s * GS_STAGE * 4;
        const uint32_t* sBu = (const uint32_t*)(gsm + s * GS_STAGE + GS_A_FLOATS);
        const int bcol = wc * 32 + g;

#pragma unroll
        for (int ks = 0; ks < 4; ks++) {
            uint32_t af[4][4], bf[4][2];
#pragma unroll
            for (int ma = 0; ma < 4; ma++)
                LDMATRIX_X4(af[ma], aS + ma * 2304 + ks * 32);
#pragma unroll
            for (int na = 0; na < 4; na++) {
                bf[na][0] = sBu[(ks * 8 + tig) * 136 + bcol + na * 8];
                bf[na][1] = sBu[(ks * 8 + tig + 4) * 136 + bcol + na * 8];
            }
#pragma unroll
            for (int ma = 0; ma < 4; ma++)
#pragma unroll
                for (int na = 0; na < 4; na++)
                    MMA_TF32(d[ma][na], af[ma], bf[na]);
        }

        if (t + 2 < T)
            issue_stage(sb + ((t + 2) % 3) * GS_STAGE * 4, A, B, tid,
                        row0, col0, (t + 2) * 32, N, K);
        asm volatile("cp.async.commit_group;" ::: "memory");
    }

#pragma unroll
    for (int ma = 0; ma < 4; ma++)
#pragma unroll
        for (int na = 0; na < 4; na++) {
            const int r = row0 + wr * 64 + ma * 16 + g;
            const int c = col0 + wc * 32 + na * 8 + tig * 2;
            float4 v = make_float4(d[ma][na][0], d[ma][na][1], d[ma][na][2], d[ma][na][3]);
            if (ROUND) {
                v.x = to_tf32(v.x); v.y = to_tf32(v.y);
                v.z = to_tf32(v.z); v.w = to_tf32(v.w);
            }
            *(float2*)&C[(size_t)r * N + c]       = make_float2(v.x, v.y);
            *(float2*)&C[(size_t)(r + 8) * N + c] = make_float2(v.z, v.w);
        }
}

// ---------------------------------------------------------------------------
// Elementwise tf32 pre-round
// ---------------------------------------------------------------------------
__global__ void round_tf32_kernel(const float* __restrict__ in, float* __restrict__ out,
                                  int n4) {
    int i = blockIdx.x * blockDim.x + threadIdx.x;
    if (i < n4) {
        float4 v = ((const float4*)in)[i];
        v.x = to_tf32(v.x); v.y = to_tf32(v.y);
        v.z = to_tf32(v.z); v.w = to_tf32(v.w);
        ((float4*)out)[i] = v;
    }
}

// ---------------------------------------------------------------------------
// Causal flash attention on tensor cores (tf32 mma.sync) — R7 pipeline:
//  * Q fragments hoisted to registers once (Q smem region reused as KV stage 0)
//  * double-buffered K/V stages with prefetch-1 (cp.async latency hidden)
//  * P round-trip is warp-private -> __syncwarp only
// Layout: K [64][68] natural (B-frag LDS banks 4g+tig distinct),
//         V [64][72] natural (banks 8tig+g distinct),
//         P [128][68] (ldmatrix phases (17r+c)%8 conflict-free).
// ---------------------------------------------------------------------------
#define FK_STRIDE 68
#define FV_STRIDE 72
#define FP_STRIDE 68
#define F_STAGE_FLOATS (64 * FK_STRIDE + 64 * FV_STRIDE)   // 8960
#define F_PS (2 * F_STAGE_FLOATS)                          // 17920
#define F_SMEM_FLOATS (F_PS + 128 * FP_STRIDE)             // 26624 floats = 106496 B

__global__ __launch_bounds__(256, 2) void flash_mma_kernel() {
    extern __shared__ __align__(16) float fsm[];
    const uint32_t sb = smem_u32(fsm);
    const int tid  = threadIdx.x;
    const int lane = tid & 31;
    const int wid  = tid >> 5;
    const int g    = lane >> 2;
    const int tig  = lane & 3;

    const int qt = (gridDim.x - 1) - blockIdx.x;     // reversed: heavy first
    const int bh = blockIdx.y;
    const int b  = bh >> 4;
    const int h  = bh & 15;
    const int q0 = qt * 128;

    const float* base = g_qkv + (size_t)b * T_SEQ * QKV_LD + h * HEAD_DIM;
    const float* Qg = base;
    const float* Kg = base + D_MODEL;
    const float* Vg = base + 2 * D_MODEL;

    // ---- prologue: Q -> stage-0 region; KV(0) -> stage 1 ----
#pragma unroll
    for (int i = 0; i < 8; i++) {
        int ff = tid + i * 256;
        int r  = ff >> 4;
        int d4 = (ff & 15) * 4;
        cp16(sb + (r * FK_STRIDE + d4) * 4, &Qg[(size_t)(q0 + r) * QKV_LD + d4]);
    }
    asm volatile("cp.async.commit_group;" ::: "memory");
#pragma unroll
    for (int i = 0; i < 4; i++) {
        int ff = tid + i * 256;
        int r  = ff >> 4;
        int d4 = (ff & 15) * 4;
        const size_t grow = (size_t)r * QKV_LD + d4;
        cp16(sb + (F_STAGE_FLOATS + r * FK_STRIDE + d4) * 4, &Kg[grow]);
        cp16(sb + (F_STAGE_FLOATS + 64 * FK_STRIDE + r * FV_STRIDE + d4) * 4, &Vg[grow]);
    }
    asm volatile("cp.async.commit_group;" ::: "memory");
    asm volatile("cp.async.wait_group 1;" ::: "memory");   // Q complete
    __syncthreads();

    // ---- extract Q fragments once (loop-invariant) ----
    const int lm_row = wid * 16 + ((lane >> 3) & 1) * 8 + (lane & 7);
    const int lm_col = ((lane >> 4) & 1) * 4;
    uint32_t qf[8][4];
    {
        const uint32_t q_lm = sb + (lm_row * FK_STRIDE + lm_col) * 4;
#pragma unroll
        for (int ks = 0; ks < 8; ks++)
            LDMATRIX_X4(qf[ks], q_lm + ks * 32);
    }
    __syncthreads();              // Q region (stage 0) now free for KV(1)

    const uint32_t p_lm = sb + (F_PS + lm_row * FP_STRIDE + lm_col) * 4;

    const float NEG_INF = __int_as_float(0xff800000u);
    const float scale = 0.125f;
    float o[8][4] = {};
    float m0 = NEG_INF, m1 = NEG_INF, l0 = 0.f, l1 = 0.f;

    const int nkt = 2 * qt + 2;
    for (int kt = 0; kt < nkt; kt++) {
        const int s = (kt + 1) & 1;          // stage holding KV(kt)

        // prefetch KV(kt+1) into the other stage (freed by bottom barrier)
        if (kt + 1 < nkt) {
            const int sd = kt & 1;
#pragma unroll
            for (int i = 0; i < 4; i++) {
                int ff = tid + i * 256;
                int r  = ff >> 4;
                int d4 = (ff & 15) * 4;
                const size_t grow = (size_t)((kt + 1) * 64 + r) * QKV_LD + d4;
                cp16(sb + (sd * F_STAGE_FLOATS + r * FK_STRIDE + d4) * 4, &Kg[grow]);
                cp16(sb + (sd * F_STAGE_FLOATS + 64 * FK_STRIDE + r * FV_STRIDE + d4) * 4,
                     &Vg[grow]);
            }
            asm volatile("cp.async.commit_group;" ::: "memory");
            asm volatile("cp.async.wait_group 1;" ::: "memory");   // KV(kt) ready
        } else {
            asm volatile("cp.async.wait_group 0;" ::: "memory");
        }
        __syncthreads();                      // KV(kt) visible to all warps

        const float* Ks = fsm + s * F_STAGE_FLOATS;
        const float* Vs = Ks + 64 * FK_STRIDE;

        // ---- S = Q K^T : 8 ks x 8 na ----
        float sfrag[8][4] = {};
#pragma unroll
        for (int ks = 0; ks < 8; ks++) {
#pragma unroll
            for (int na = 0; na < 8; na++) {
                uint32_t bf[2];
                bf[0] = __float_as_uint(Ks[(na * 8 + g) * FK_STRIDE + ks * 8 + tig]);
                bf[1] = __float_as_uint(Ks[(na * 8 + g) * FK_STRIDE + ks * 8 + tig + 4]);
                MMA_TF32(sfrag[na], qf[ks], bf);
            }
        }

        // ---- scale + causal mask ----
        const bool diag = (kt >= 2 * qt);
        const int qr0 = q0 + wid * 16 + g;
        const int qr1 = qr0 + 8;
#pragma unroll
        for (int na = 0; na < 8; na++) {
            const int kg = kt * 64 + na * 8 + 2 * tig;
            sfrag[na][0] *= scale; sfrag[na][1] *= scale;
            sfrag[na][2] *= scale; sfrag[na][3] *= scale;
            if (diag) {
                if (kg     > qr0) sfrag[na][0] = NEG_INF;
                if (kg + 1 > qr0) sfrag[na][1] = NEG_INF;
                if (kg     > qr1) sfrag[na][2] = NEG_INF;
                if (kg + 1 > qr1) sfrag[na][3] = NEG_INF;
            }
        }

        // ---- online softmax (rows g / g+8; reduce across quad tig) ----
        float mx0 = NEG_INF, mx1 = NEG_INF;
#pragma unroll
        for (int na = 0; na < 8; na++) {
            mx0 = fmaxf(mx0, fmaxf(sfrag[na][0], sfrag[na][1]));
            mx1 = fmaxf(mx1, fmaxf(sfrag[na][2], sfrag[na][3]));
        }
        mx0 = fmaxf(mx0, __shfl_xor_sync(0xffffffffu, mx0, 1));
        mx0 = fmaxf(mx0, __shfl_xor_sync(0xffffffffu, mx0, 2));
        mx1 = fmaxf(mx1, __shfl_xor_sync(0xffffffffu, mx1, 1));
        mx1 = fmaxf(mx1, __shfl_xor_sync(0xffffffffu, mx1, 2));
        const float mn0 = fmaxf(m0, mx0);
        const float mn1 = fmaxf(m1, mx1);
        const float a0 = __expf(m0 - mn0);
        const float a1 = __expf(m1 - mn1);
        float sum0 = 0.f, sum1 = 0.f;
#pragma unroll
        for (int na = 0; na < 8; na++) {
            sfrag[na][0] = __expf(sfrag[na][0] - mn0);
            sfrag[na][1] = __expf(sfrag[na][1] - mn0);
            sfrag[na][2] = __expf(sfrag[na][2] - mn1);
            sfrag[na][3] = __expf(sfrag[na][3] - mn1);
            sum0 += sfrag[na][0] + sfrag[na][1];
            sum1 += sfrag[na][2] + sfrag[na][3];
        }
        sum0 += __shfl_xor_sync(0xffffffffu, sum0, 1);
        sum0 += __shfl_xor_sync(0xffffffffu, sum0, 2);
        sum1 += __shfl_xor_sync(0xffffffffu, sum1, 1);
        sum1 += __shfl_xor_sync(0xffffffffu, sum1, 2);
        l0 = l0 * a0 + sum0;  m0 = mn0;
        l1 = l1 * a1 + sum1;  m1 = mn1;
#pragma unroll
        for (int na = 0; na < 8; na++) {
            o[na][0] *= a0; o[na][1] *= a0;
            o[na][2] *= a1; o[na][3] *= a1;
        }

        // ---- P (tf32) -> warp-private smem rows; __syncwarp suffices ----
        {
            const int pr0 = wid * 16 + g;
            const int kc  = 2 * tig;
#pragma unroll
            for (int na = 0; na < 8; na++) {
                *(float2*)&fsm[F_PS + pr0 * FP_STRIDE + na * 8 + kc] =
                    make_float2(to_tf32(sfrag[na][0]), to_tf32(sfrag[na][1]));
                *(float2*)&fsm[F_PS + (pr0 + 8) * FP_STRIDE + na * 8 + kc] =
                    make_float2(to_tf32(sfrag[na][2]), to_tf32(sfrag[na][3]));
            }
        }
        __syncwarp();

        // ---- O += P V : 8 ks(key) x 8 na(d) ----
#pragma unroll
        for (int ks = 0; ks < 8; ks++) {
            uint32_t af[4];
            LDMATRIX_X4(af, p_lm + ks * 32);
#pragma unroll
            for (int na = 0; na < 8; na++) {
                uint32_t bf[2];
                bf[0] = __float_as_uint(Vs[(ks * 8 + tig) * FV_STRIDE + na * 8 + g]);
                bf[1] = __float_as_uint(Vs[(ks * 8 + tig + 4) * FV_STRIDE + na * 8 + g]);
                MMA_TF32(o[na], af, bf);
            }
        }
        __syncthreads();          // all warps done with stage s -> reusable
    }

    // ---- epilogue: /l, tf32-round (A operand of out-proj), store ----
    const float i0 = 1.f / l0;
    const float i1 = 1.f / l1;
    const int r0 = q0 + wid * 16 + g;
    float* out0 = &g_attn[(size_t)(b * T_SEQ + r0) * D_MODEL + h * HEAD_DIM + 2 * tig];
    float* out1 = &g_attn[(size_t)(b * T_SEQ + r0 + 8) * D_MODEL + h * HEAD_DIM + 2 * tig];
#pragma unroll
    for (int na = 0; na < 8; na++) {
        *(float2*)&out0[na * 8] = make_float2(to_tf32(o[na][0] * i0), to_tf32(o[na][1] * i0));
        *(float2*)&out1[na * 8] = make_float2(to_tf32(o[na][2] * i1), to_tf32(o[na][3] * i1));
    }
}

// ---------------------------------------------------------------------------
// Launch
// ---------------------------------------------------------------------------
extern "C" void kernel_launch(void* const* d_in, const int* in_sizes, int n_in,
                              void* d_out, int out_size) {
    const float* x     = (const float*)d_in[0];   // [2,2048,1024]
    const float* w_qkv = (const float*)d_in[1];   // [1024,3072]
    const float* w_out = (const float*)d_in[2];   // [1024,1024]
    float* out = (float*)d_out;                   // [2,2048,1024]

    void *qkv_p, *attn_p, *xr_p, *wqkv_p, *wout_p;
    cudaGetSymbolAddress(&qkv_p,  g_qkv);
    cudaGetSymbolAddress(&attn_p, g_attn);
    cudaGetSymbolAddress(&xr_p,   g_xr);
    cudaGetSymbolAddress(&wqkv_p, g_wqkv_r);
    cudaGetSymbolAddress(&wout_p, g_wout_r);

    const int fa_smem = F_SMEM_FLOATS * (int)sizeof(float);    // 106496 B
    cudaFuncSetAttribute(flash_mma_kernel,
                         cudaFuncAttributeMaxDynamicSharedMemorySize, fa_smem);
    cudaFuncSetAttribute(gemm_mma<true>,
                         cudaFuncAttributeMaxDynamicSharedMemorySize, GS_SMEM_BYTES);
    cudaFuncSetAttribute(gemm_mma<false>,
                         cudaFuncAttributeMaxDynamicSharedMemorySize, GS_SMEM_BYTES);

    // 0) pre-round inputs to tf32
    {
        int n4 = M_TOTAL * D_MODEL / 4;
        round_tf32_kernel<<<(n4 + 255) / 256, 256>>>(x, (float*)xr_p, n4);
        n4 = D_MODEL * QKV_LD / 4;
        round_tf32_kernel<<<(n4 + 255) / 256, 256>>>(w_qkv, (float*)wqkv_p, n4);
        n4 = D_MODEL * D_MODEL / 4;
        round_tf32_kernel<<<(n4 + 255) / 256, 256>>>(w_out, (float*)wout_p, n4);
    }

    // 1) QKV projection (output tf32-rounded for flash's tensor-core consumption)
    gemm_mma<true><<<dim3(QKV_LD / 128, M_TOTAL / 128), 256, GS_SMEM_BYTES>>>(
        (const float*)xr_p, (const float*)wqkv_p, (float*)qkv_p,
        M_TOTAL, QKV_LD, D_MODEL);

    // 2) causal flash attention (tensor cores, pipelined)
    flash_mma_kernel<<<dim3(T_SEQ / 128, BATCH * N_HEADS), 256, fa_smem>>>();

    // 3) output projection
    gemm_mma<false><<<dim3(D_MODEL / 128, M_TOTAL / 128), 256, GS_SMEM_BYTES>>>(
        (const float*)attn_p, (const float*)wout_p, out,
        M_TOTAL, D_MODEL, D_MODEL);
}